// round 10
// baseline (speedup 1.0000x reference)
#include <cuda_runtime.h>
#include <cuda_fp16.h>
#include <cstdint>

typedef unsigned long long u64;
typedef unsigned int u32;
typedef unsigned short u16;

#define NUM_CITIES 50000
#define EMB 50
#define HID 64
#define G4 256          // 4 * HID
#define BATCH 1024
#define SEQ 512
#define K3_CTAS 391     // ceil(50000/128)
#define HSTRIDE 72      // fp16 h row stride (halfs)
#define TSP 132         // pass2 transpose tile row stride (floats)

// Scratch (no allocation allowed -> device globals)
// NOTE layout: g_emb_proj[row][k*4 + G]  (gate-interleaved!)
__device__ float  g_emb_proj[NUM_CITIES * G4];
__device__ __half g_hfin_h[BATCH * HID];          // final hidden state (fp16)
__device__ float  g_partial[K3_CTAS * BATCH];     // per-CTA row partial sums
__device__ float  g_rowinv[BATCH];                // 1/rowsum

// ---------------------------------------------------------------------------
// helpers
// ---------------------------------------------------------------------------
__device__ __forceinline__ float fast_ex2(float x) {
    float r; asm("ex2.approx.f32 %0, %1;" : "=f"(r) : "f"(x)); return r;
}
__device__ __forceinline__ u32 h2tanh(u32 v) {            // 2 tanh per MUFU op
    u32 r; asm("tanh.approx.f16x2 %0, %1;" : "=r"(r) : "r"(v)); return r;
}
__device__ __forceinline__ u32 pack_h2(float a, float b) {
    half2 h = __floats2half2_rn(a, b);
    return *reinterpret_cast<u32*>(&h);
}
__device__ __forceinline__ void unpack2(u64 v, float& lo, float& hi) {
    asm("mov.b64 {%0,%1}, %2;" : "=f"(lo), "=f"(hi) : "l"(v));
}
__device__ __forceinline__ u64 pack2(float lo, float hi) {
    u64 v; asm("mov.b64 %0, {%1,%2};" : "=l"(v) : "f"(lo), "f"(hi)); return v;
}
__device__ __forceinline__ void fma2(u64& acc, u64 a, u64 b) {
    asm("fma.rn.f32x2 %0, %1, %2, %0;" : "+l"(acc) : "l"(a), "l"(b));
}
__device__ __forceinline__ void hmma16816(
    float& d0, float& d1, float& d2, float& d3,
    u32 a0, u32 a1, u32 a2, u32 a3, u32 b0, u32 b1)
{
    asm("mma.sync.aligned.m16n8k16.row.col.f32.f16.f16.f32 "
        "{%0,%1,%2,%3}, {%4,%5,%6,%7}, {%8,%9}, {%0,%1,%2,%3};"
        : "+f"(d0), "+f"(d1), "+f"(d2), "+f"(d3)
        : "r"(a0), "r"(a1), "r"(a2), "r"(a3), "r"(b0), "r"(b1));
}
__device__ __forceinline__ u32 w_half2(const float* __restrict__ W, int j, int k) {
    float2 f = *reinterpret_cast<const float2*>(W + j * HID + k);
    half2 h = __float22half2_rn(f);
    return *reinterpret_cast<u32*>(&h);
}

// no-op launch-slot shifter (keeps ncu's fixed sample index on k2)
__global__ void k_nop() {}

// ---------------------------------------------------------------------------
// K1: emb_proj[r][kk*4+G] = sum emb[r]·W_ih[64G+kk] + bias(64G+kk)
// thread j handles output slot j: G=j&3, kk=j>>2 -> W row 64*(j&3)+(j>>2).
// Stores stay fully coalesced.
// ---------------------------------------------------------------------------
__global__ void __launch_bounds__(256) k1_embproj(
    const float* __restrict__ emb, const float* __restrict__ W_ih,
    const float* __restrict__ b_ih, const float* __restrict__ b_hh)
{
    __shared__ __align__(16) float es[80][52];
    const int j   = threadIdx.x;
    const int row = 64 * (j & 3) + (j >> 2);     // gate-interleaved mapping
    const int r0  = blockIdx.x * 80;

    u64 wk[26];
    {
        const float2* wr = reinterpret_cast<const float2*>(W_ih + row * 50);
#pragma unroll
        for (int m = 0; m < 25; m++) {
            float2 t = __ldg(&wr[m]);
            wk[m] = pack2(t.x, t.y);
        }
        wk[25] = 0ull;
    }
    const u64 biasp = pack2(b_ih[row] + b_hh[row], 0.0f);

    for (int idx = j; idx < 80 * 50; idx += 256)
        es[idx / 50][idx % 50] = emb[(r0 + idx / 50) * 50 + (idx % 50)];
    if (j < 160) es[j >> 1][50 + (j & 1)] = 0.0f;
    __syncthreads();

#pragma unroll 4
    for (int r = 0; r < 80; r++) {
        u64 acc = biasp;
#pragma unroll
        for (int m = 0; m < 13; m++) {
            ulonglong2 e2 = *reinterpret_cast<const ulonglong2*>(&es[r][m * 4]);
            fma2(acc, e2.x, wk[2 * m]);
            fma2(acc, e2.y, wk[2 * m + 1]);
        }
        float lo, hi; unpack2(acc, lo, hi);
        g_emb_proj[(r0 + r) * G4 + j] = lo + hi;
    }
}

// ---------------------------------------------------------------------------
// K2: LSTM recurrence, HMMA, ONE barrier per step, NO shfl.
// grid 256 x 128 thr, 4 batches/CTA, 2 CTAs/SM.
// Lane (g,t4) update pairs (t4<2 only): (k1=16w+g, b=2t4), (k1,b+1),
// (k2=k1+8, b), (k2, b+1) — D frags land exactly there. gx via float4
// (gate-interleaved emb_proj).
// ---------------------------------------------------------------------------
__global__ void __launch_bounds__(128, 2) k2_lstm(
    const int* __restrict__ x, const float* __restrict__ W_hh)
{
    __shared__ __align__(16) __half hS[2][8 * HSTRIDE];
    __shared__ u16 tokS[4][SEQ];

    const int tid  = threadIdx.x;
    const int lane = tid & 31;
    const int w    = tid >> 5;
    const int g    = lane >> 2;
    const int t4   = lane & 3;
    const int b0   = blockIdx.x * 4;

    const bool act = (t4 < 2);
    const int k1v = 16 * w + g;
    const int k2v = k1v + 8;
    const int bA  = 2 * t4;          // valid batch only when act
    const int bB  = bA + 1;

    // stationary A-fragments: gate G rows j = 64G + 16w + g(+8)
    u32 A[4][4][4];
#pragma unroll
    for (int G = 0; G < 4; G++) {
        const int j = 64 * G + 16 * w + g;
#pragma unroll
        for (int K = 0; K < 4; K++) {
            const int c = 16 * K + 2 * t4;
            A[G][K][0] = w_half2(W_hh, j,     c);
            A[G][K][1] = w_half2(W_hh, j + 8, c);
            A[G][K][2] = w_half2(W_hh, j,     c + 8);
            A[G][K][3] = w_half2(W_hh, j + 8, c + 8);
        }
    }

    {
        __half* hz = &hS[0][0];
        for (int i = tid; i < 2 * 8 * HSTRIDE; i += 128) hz[i] = __float2half(0.0f);
    }
    for (int i = tid; i < 4 * SEQ; i += 128) {
        const int b = i >> 9, t = i & (SEQ - 1);
        tokS[b][t] = (u16)__ldg(&x[(b0 + b) * SEQ + t]);
    }

    float4 gx00, gx01, gx10, gx11;   // (k1,bA) (k1,bB) (k2,bA) (k2,bB)
    gx00 = gx01 = gx10 = gx11 = make_float4(0.f, 0.f, 0.f, 0.f);
    if (act) {
        const int tokA = __ldg(&x[(b0 + bA) * SEQ]);
        const int tokB = __ldg(&x[(b0 + bB) * SEQ]);
        gx00 = *reinterpret_cast<const float4*>(g_emb_proj + (size_t)tokA * G4 + k1v * 4);
        gx01 = *reinterpret_cast<const float4*>(g_emb_proj + (size_t)tokB * G4 + k1v * 4);
        gx10 = *reinterpret_cast<const float4*>(g_emb_proj + (size_t)tokA * G4 + k2v * 4);
        gx11 = *reinterpret_cast<const float4*>(g_emb_proj + (size_t)tokB * G4 + k2v * 4);
    }
    float c00 = 0.f, c01 = 0.f, c10 = 0.f, c11 = 0.f;
    float h00 = 0.f, h01 = 0.f, h10 = 0.f, h11 = 0.f;

    __syncthreads();

    for (int t = 0; t < SEQ; t++) {
        const int buf = t & 1;
        const __half* hb = hS[buf];

        // ---- 16 HMMA ----
        float D[4][4];
#pragma unroll
        for (int G = 0; G < 4; G++) {
            D[G][0] = 0.f; D[G][1] = 0.f; D[G][2] = 0.f; D[G][3] = 0.f;
        }
#pragma unroll
        for (int K = 0; K < 4; K++) {
            const int kk = 16 * K + 2 * t4;
            u32 bb0 = *reinterpret_cast<const u32*>(&hb[g * HSTRIDE + kk]);
            u32 bb1 = *reinterpret_cast<const u32*>(&hb[g * HSTRIDE + kk + 8]);
#pragma unroll
            for (int G = 0; G < 4; G++)
                hmma16816(D[G][0], D[G][1], D[G][2], D[G][3],
                          A[G][K][0], A[G][K][1], A[G][K][2], A[G][K][3], bb0, bb1);
        }

        // ---- prefetch gx(t+1) (float4, gate-interleaved) ----
        float4 n00, n01, n10, n11;
        if (act) {
            const int tn = (t + 1 < SEQ) ? (t + 1) : (SEQ - 1);
            const int tokA = tokS[bA][tn];
            const int tokB = tokS[bB][tn];
            n00 = *reinterpret_cast<const float4*>(g_emb_proj + (size_t)tokA * G4 + k1v * 4);
            n01 = *reinterpret_cast<const float4*>(g_emb_proj + (size_t)tokB * G4 + k1v * 4);
            n10 = *reinterpret_cast<const float4*>(g_emb_proj + (size_t)tokA * G4 + k2v * 4);
            n11 = *reinterpret_cast<const float4*>(g_emb_proj + (size_t)tokB * G4 + k2v * 4);
        }

        if (act) {
            // pre-activations: D[G][0]=(k1,bA) D[G][1]=(k1,bB) D[G][2]=(k2,bA) D[G][3]=(k2,bB)
            float xi0 = D[0][0] + gx00.x, xi1 = D[0][1] + gx01.x;
            float xi2 = D[0][2] + gx10.x, xi3 = D[0][3] + gx11.x;
            float xf0 = D[1][0] + gx00.y, xf1 = D[1][1] + gx01.y;
            float xf2 = D[1][2] + gx10.y, xf3 = D[1][3] + gx11.y;
            float xg0 = D[2][0] + gx00.z, xg1 = D[2][1] + gx01.z;
            float xg2 = D[2][2] + gx10.z, xg3 = D[2][3] + gx11.z;
            float xo0 = D[3][0] + gx00.w, xo1 = D[3][1] + gx01.w;
            float xo2 = D[3][2] + gx10.w, xo3 = D[3][3] + gx11.w;

            u32 tiA = h2tanh(pack_h2(0.5f * xi0, 0.5f * xi1));
            u32 tiB = h2tanh(pack_h2(0.5f * xi2, 0.5f * xi3));
            u32 tfA = h2tanh(pack_h2(0.5f * xf0, 0.5f * xf1));
            u32 tfB = h2tanh(pack_h2(0.5f * xf2, 0.5f * xf3));
            u32 tgA = h2tanh(pack_h2(xg0, xg1));
            u32 tgB = h2tanh(pack_h2(xg2, xg3));
            u32 toA = h2tanh(pack_h2(0.5f * xo0, 0.5f * xo1));
            u32 toB = h2tanh(pack_h2(0.5f * xo2, 0.5f * xo3));

            half2 hiA = *reinterpret_cast<half2*>(&tiA), hiB = *reinterpret_cast<half2*>(&tiB);
            half2 hfA = *reinterpret_cast<half2*>(&tfA), hfB = *reinterpret_cast<half2*>(&tfB);
            half2 hgA = *reinterpret_cast<half2*>(&tgA), hgB = *reinterpret_cast<half2*>(&tgB);
            half2 hoA = *reinterpret_cast<half2*>(&toA), hoB = *reinterpret_cast<half2*>(&toB);

            float i0 = fmaf(0.5f, __low2float(hiA), 0.5f), i1 = fmaf(0.5f, __high2float(hiA), 0.5f);
            float i2 = fmaf(0.5f, __low2float(hiB), 0.5f), i3 = fmaf(0.5f, __high2float(hiB), 0.5f);
            float f0 = fmaf(0.5f, __low2float(hfA), 0.5f), f1 = fmaf(0.5f, __high2float(hfA), 0.5f);
            float f2 = fmaf(0.5f, __low2float(hfB), 0.5f), f3 = fmaf(0.5f, __high2float(hfB), 0.5f);
            float g0 = __low2float(hgA), g1 = __high2float(hgA);
            float g2 = __low2float(hgB), g3 = __high2float(hgB);
            float o0 = fmaf(0.5f, __low2float(hoA), 0.5f), o1 = fmaf(0.5f, __high2float(hoA), 0.5f);
            float o2 = fmaf(0.5f, __low2float(hoB), 0.5f), o3 = fmaf(0.5f, __high2float(hoB), 0.5f);

            c00 = fmaf(f0, c00, i0 * g0);
            c01 = fmaf(f1, c01, i1 * g1);
            c10 = fmaf(f2, c10, i2 * g2);
            c11 = fmaf(f3, c11, i3 * g3);

            u32 tcA = h2tanh(pack_h2(c00, c01));
            u32 tcB = h2tanh(pack_h2(c10, c11));
            half2 hcA = *reinterpret_cast<half2*>(&tcA), hcB = *reinterpret_cast<half2*>(&tcB);
            h00 = o0 * __low2float(hcA);  h01 = o1 * __high2float(hcA);
            h10 = o2 * __low2float(hcB);  h11 = o3 * __high2float(hcB);

            __half* hn = hS[buf ^ 1];
            hn[bA * HSTRIDE + k1v] = __float2half(h00);
            hn[bB * HSTRIDE + k1v] = __float2half(h01);
            hn[bA * HSTRIDE + k2v] = __float2half(h10);
            hn[bB * HSTRIDE + k2v] = __float2half(h11);

            gx00 = n00; gx01 = n01; gx10 = n10; gx11 = n11;
        }

        __syncthreads();
    }

    if (act) {
        g_hfin_h[(b0 + bA) * HID + k1v] = __float2half(h00);
        g_hfin_h[(b0 + bB) * HID + k1v] = __float2half(h01);
        g_hfin_h[(b0 + bA) * HID + k2v] = __float2half(h10);
        g_hfin_h[(b0 + bB) * HID + k2v] = __float2half(h11);
    }
}

// ---------------------------------------------------------------------------
// K3: tensor-core FC, two-pass. store=0: exp row-sums -> g_partial.
// store=1: recompute, scale, stage 64x128 tile in smem, coalesced f4 stores.
// ---------------------------------------------------------------------------
__global__ void __launch_bounds__(256) k3_fc(
    const float* __restrict__ W_fc, const float* __restrict__ b_fc,
    float* __restrict__ out, int store)
{
    __shared__ __align__(16) __half hs[64 * HSTRIDE];
    __shared__ float ws[8][64];
    __shared__ float riS[64];
    __shared__ __align__(16) float ts[64 * TSP];   // transpose tile (pass2)

    const int tid  = threadIdx.x;
    const int lane = tid & 31;
    const int w    = tid >> 5;
    const int g    = lane >> 2;
    const int t4   = lane & 3;

    const int cb   = blockIdx.x * 128;
    const int j1   = cb + 16 * w + g;
    const int j2   = j1 + 8;
    const bool v1  = (j1 < NUM_CITIES);
    const bool v2  = (j2 < NUM_CITIES);
    const int c1   = 16 * w + g;        // CTA-local city col
    const int c2   = c1 + 8;

    u32 A[4][4];
#pragma unroll
    for (int K = 0; K < 4; K++) {
        const int c = 16 * K + 2 * t4;
        A[K][0] = v1 ? w_half2(W_fc, j1, c)     : 0u;
        A[K][1] = v2 ? w_half2(W_fc, j2, c)     : 0u;
        A[K][2] = v1 ? w_half2(W_fc, j1, c + 8) : 0u;
        A[K][3] = v2 ? w_half2(W_fc, j2, c + 8) : 0u;
    }
    const float bias1 = v1 ? __ldg(&b_fc[j1]) : 0.0f;
    const float bias2 = v2 ? __ldg(&b_fc[j2]) : 0.0f;

    const u32* hsrc = reinterpret_cast<const u32*>(g_hfin_h);

    for (int chunk = 0; chunk < 16; chunk++) {
        const int cb64 = chunk * 64;
        __syncthreads();
        for (int i = tid; i < 64 * 32; i += 256) {
            const int r = i >> 5;
            const int cp = i & 31;
            *reinterpret_cast<u32*>(&hs[r * HSTRIDE + 2 * cp]) =
                __ldg(&hsrc[(cb64 + r) * 32 + cp]);
        }
        if (store && tid < 64) riS[tid] = g_rowinv[cb64 + tid];
        __syncthreads();

#pragma unroll
        for (int nt = 0; nt < 8; nt++) {
            float d0 = 0.f, d1 = 0.f, d2 = 0.f, d3 = 0.f;
#pragma unroll
            for (int K = 0; K < 4; K++) {
                const int kk = 16 * K + 2 * t4;
                const __half* hrow = &hs[(nt * 8 + g) * HSTRIDE];
                u32 bb0 = *reinterpret_cast<const u32*>(&hrow[kk]);
                u32 bb1 = *reinterpret_cast<const u32*>(&hrow[kk + 8]);
                hmma16816(d0, d1, d2, d3, A[K][0], A[K][1], A[K][2], A[K][3], bb0, bb1);
            }
            const float LOG2E = 1.4426950408889634f;
            float e0 = v1 ? fast_ex2((d0 + bias1) * LOG2E) : 0.0f;
            float e1 = v1 ? fast_ex2((d1 + bias1) * LOG2E) : 0.0f;
            float e2 = v2 ? fast_ex2((d2 + bias2) * LOG2E) : 0.0f;
            float e3 = v2 ? fast_ex2((d3 + bias2) * LOG2E) : 0.0f;

            if (store) {
                const int r0i = nt * 8 + 2 * t4;
                const float rv0 = riS[r0i];
                const float rv1 = riS[r0i + 1];
                ts[r0i * TSP + c1]       = e0 * rv0;
                ts[(r0i + 1) * TSP + c1] = e1 * rv1;
                ts[r0i * TSP + c2]       = e2 * rv0;
                ts[(r0i + 1) * TSP + c2] = e3 * rv1;
            } else {
                float s0 = e0 + e2;
                float s1 = e1 + e3;
#pragma unroll
                for (int m = 4; m <= 16; m <<= 1) {
                    s0 += __shfl_xor_sync(0xffffffffu, s0, m);
                    s1 += __shfl_xor_sync(0xffffffffu, s1, m);
                }
                if (g == 0) {
                    ws[w][nt * 8 + 2 * t4]     = s0;
                    ws[w][nt * 8 + 2 * t4 + 1] = s1;
                }
            }
        }

        if (store) {
            __syncthreads();
            // coalesced float4 stores of the 64 x 128 tile
            for (int i = tid; i < 64 * 32; i += 256) {
                const int r  = i >> 5;
                const int c4 = i & 31;
                if (cb + 4 * c4 + 3 < NUM_CITIES) {
                    float4 v = *reinterpret_cast<const float4*>(&ts[r * TSP + 4 * c4]);
                    __stcs(reinterpret_cast<float4*>(
                        out + (size_t)(cb64 + r) * NUM_CITIES + cb + 4 * c4), v);
                }
            }
        } else {
            __syncthreads();
            if (tid < 64) {
                float s = 0.0f;
#pragma unroll
                for (int ww = 0; ww < 8; ww++) s += ws[ww][tid];
                g_partial[blockIdx.x * BATCH + cb64 + tid] = s;
            }
        }
    }
}

// ---------------------------------------------------------------------------
// K3c: exact row-sum inverses. One warp per batch row.
// ---------------------------------------------------------------------------
__global__ void __launch_bounds__(128) k3c_inv()
{
    const int warp = (blockIdx.x * 128 + threadIdx.x) >> 5;
    const int lane = threadIdx.x & 31;
    float s = 0.0f;
    for (int cta = lane; cta < K3_CTAS; cta += 32)
        s += g_partial[cta * BATCH + warp];
    s += __shfl_xor_sync(0xffffffffu, s, 16);
    s += __shfl_xor_sync(0xffffffffu, s, 8);
    s += __shfl_xor_sync(0xffffffffu, s, 4);
    s += __shfl_xor_sync(0xffffffffu, s, 2);
    s += __shfl_xor_sync(0xffffffffu, s, 1);
    if (lane == 0) g_rowinv[warp] = 1.0f / s;
}

// ---------------------------------------------------------------------------
extern "C" void kernel_launch(void* const* d_in, const int* in_sizes, int n_in,
                              void* d_out, int out_size)
{
    (void)in_sizes; (void)n_in; (void)out_size;
    const int*   x    = (const int*)  d_in[0];
    const float* emb  = (const float*)d_in[1];
    const float* W_ih = (const float*)d_in[2];
    const float* W_hh = (const float*)d_in[3];
    const float* b_ih = (const float*)d_in[4];
    const float* b_hh = (const float*)d_in[5];
    const float* W_fc = (const float*)d_in[6];
    const float* b_fc = (const float*)d_in[7];
    float* out = (float*)d_out;

    k1_embproj<<<NUM_CITIES / 80, 256>>>(emb, W_ih, b_ih, b_hh);
    k_nop<<<1, 32>>>();
    k_nop<<<1, 32>>>();
    k2_lstm<<<BATCH / 4, 128>>>(x, W_hh);          // launch idx 3 -> profiled
    k3_fc<<<K3_CTAS, 256>>>(W_fc, b_fc, out, 0);   // pass 1: sums
    k3c_inv<<<256, 128>>>();
    k3_fc<<<K3_CTAS, 256>>>(W_fc, b_fc, out, 1);   // pass 2: normalized store
}

// round 11
// speedup vs baseline: 1.2464x; 1.2464x over previous
#include <cuda_runtime.h>
#include <cuda_fp16.h>
#include <cstdint>

typedef unsigned long long u64;
typedef unsigned int u32;
typedef unsigned short u16;

#define NUM_CITIES 50000
#define EMB 50
#define HID 64
#define G4 256          // 4 * HID
#define BATCH 1024
#define SEQ 512
#define K3_CTAS 391     // ceil(50000/128)
#define HSTRIDE 72      // fp16 h row stride (halfs)

// Scratch (no allocation allowed -> device globals)
// layout: g_emb_proj[row][u*4 + G]  (gate-interleaved)
__device__ float  g_emb_proj[NUM_CITIES * G4];
__device__ __half g_hfin_h[BATCH * HID];          // final hidden state (fp16)
__device__ float  g_partial[K3_CTAS * BATCH];     // per-CTA row partial sums
__device__ float  g_rowinv[BATCH];                // 1/rowsum

// ---------------------------------------------------------------------------
// helpers
// ---------------------------------------------------------------------------
__device__ __forceinline__ float fast_ex2(float x) {
    float r; asm("ex2.approx.f32 %0, %1;" : "=f"(r) : "f"(x)); return r;
}
__device__ __forceinline__ u32 h2tanh(u32 v) {            // 2 tanh per MUFU op
    u32 r; asm("tanh.approx.f16x2 %0, %1;" : "=r"(r) : "r"(v)); return r;
}
__device__ __forceinline__ u32 pack_h2(float a, float b) {
    half2 h = __floats2half2_rn(a, b);
    return *reinterpret_cast<u32*>(&h);
}
__device__ __forceinline__ void unpack2(u64 v, float& lo, float& hi) {
    asm("mov.b64 {%0,%1}, %2;" : "=f"(lo), "=f"(hi) : "l"(v));
}
__device__ __forceinline__ u64 pack2(float lo, float hi) {
    u64 v; asm("mov.b64 %0, {%1,%2};" : "=l"(v) : "f"(lo), "f"(hi)); return v;
}
__device__ __forceinline__ void fma2(u64& acc, u64 a, u64 b) {
    asm("fma.rn.f32x2 %0, %1, %2, %0;" : "+l"(acc) : "l"(a), "l"(b));
}
__device__ __forceinline__ void hmma16816(
    float& d0, float& d1, float& d2, float& d3,
    u32 a0, u32 a1, u32 a2, u32 a3, u32 b0, u32 b1)
{
    asm("mma.sync.aligned.m16n8k16.row.col.f32.f16.f16.f32 "
        "{%0,%1,%2,%3}, {%4,%5,%6,%7}, {%8,%9}, {%0,%1,%2,%3};"
        : "+f"(d0), "+f"(d1), "+f"(d2), "+f"(d3)
        : "r"(a0), "r"(a1), "r"(a2), "r"(a3), "r"(b0), "r"(b1));
}
__device__ __forceinline__ u32 w_half2(const float* __restrict__ W, int j, int k) {
    float2 f = *reinterpret_cast<const float2*>(W + j * HID + k);
    half2 h = __float22half2_rn(f);
    return *reinterpret_cast<u32*>(&h);
}

// no-op launch-slot shifter (keeps ncu's fixed sample index on k2)
__global__ void k_nop() {}

// ---------------------------------------------------------------------------
// K1: emb_proj[r][u*4+G] = emb[r]·W_ih[64G+u] + bias(64G+u)
// thread j -> slot j: u=j>>2, G=j&3 -> W row 64*(j&3)+(j>>2). Coalesced stores.
// ---------------------------------------------------------------------------
__global__ void __launch_bounds__(256) k1_embproj(
    const float* __restrict__ emb, const float* __restrict__ W_ih,
    const float* __restrict__ b_ih, const float* __restrict__ b_hh)
{
    __shared__ __align__(16) float es[80][52];
    const int j   = threadIdx.x;
    const int row = 64 * (j & 3) + (j >> 2);     // gate-interleaved mapping
    const int r0  = blockIdx.x * 80;

    u64 wk[26];
    {
        const float2* wr = reinterpret_cast<const float2*>(W_ih + row * 50);
#pragma unroll
        for (int m = 0; m < 25; m++) {
            float2 t = __ldg(&wr[m]);
            wk[m] = pack2(t.x, t.y);
        }
        wk[25] = 0ull;
    }
    const u64 biasp = pack2(b_ih[row] + b_hh[row], 0.0f);

    for (int idx = j; idx < 80 * 50; idx += 256)
        es[idx / 50][idx % 50] = emb[(r0 + idx / 50) * 50 + (idx % 50)];
    if (j < 160) es[j >> 1][50 + (j & 1)] = 0.0f;
    __syncthreads();

#pragma unroll 4
    for (int r = 0; r < 80; r++) {
        u64 acc = biasp;
#pragma unroll
        for (int m = 0; m < 13; m++) {
            ulonglong2 e2 = *reinterpret_cast<const ulonglong2*>(&es[r][m * 4]);
            fma2(acc, e2.x, wk[2 * m]);
            fma2(acc, e2.y, wk[2 * m + 1]);
        }
        float lo, hi; unpack2(acc, lo, hi);
        g_emb_proj[(r0 + r) * G4 + j] = lo + hi;
    }
}

// ---------------------------------------------------------------------------
// K2: LSTM recurrence. 128 CTAs x 256 threads (8 warps), 8 batches/CTA.
// Gate-paired tiling: warp w owns hidden units u in [8w, 8w+8).
//   tile0 rows = { i(u), f(u) }  (16 rows), tile1 rows = { g(u), o(u) }.
// N = 8 batches, ALL REAL. 8 HMMA/warp/step, split-K (2 serial).
// D-frag ownership gives each lane i,f,g,o for (u=8w+g, b=2t4 & 2t4+1):
// register-local update, no shfl, no divergence. One barrier per step.
// ---------------------------------------------------------------------------
__global__ void __launch_bounds__(256, 1) k2_lstm(
    const int* __restrict__ x, const float* __restrict__ W_hh)
{
    __shared__ __align__(16) __half hS[2][8 * HSTRIDE];
    __shared__ u16 tokS[8][SEQ];

    const int tid  = threadIdx.x;
    const int lane = tid & 31;
    const int w    = tid >> 5;          // warp 0..7
    const int g    = lane >> 2;         // 0..7
    const int t4   = lane & 3;          // 0..3
    const int b0   = blockIdx.x * 8;

    const int u  = 8 * w + g;           // hidden unit owned by this lane
    const int bA = 2 * t4;              // lane's two batches
    const int bB = bA + 1;

    // stationary A-fragments. tile0: rows g->i(u), g+8->f(u). tile1: g/o.
    u32 A0[4][4], A1[4][4];
#pragma unroll
    for (int K = 0; K < 4; K++) {
        const int c = 16 * K + 2 * t4;
        A0[K][0] = w_half2(W_hh,       u, c);      // i
        A0[K][1] = w_half2(W_hh,  64 + u, c);      // f
        A0[K][2] = w_half2(W_hh,       u, c + 8);
        A0[K][3] = w_half2(W_hh,  64 + u, c + 8);
        A1[K][0] = w_half2(W_hh, 128 + u, c);      // g
        A1[K][1] = w_half2(W_hh, 192 + u, c);      // o
        A1[K][2] = w_half2(W_hh, 128 + u, c + 8);
        A1[K][3] = w_half2(W_hh, 192 + u, c + 8);
    }

    // zero h buffers
    {
        __half* hz = &hS[0][0];
        for (int i = tid; i < 2 * 8 * HSTRIDE; i += 256) hz[i] = __float2half(0.0f);
    }
    // preload all tokens (u16)
    for (int i = tid; i < 8 * SEQ; i += 256) {
        const int b = i >> 9, t = i & (SEQ - 1);
        tokS[b][t] = (u16)__ldg(&x[(b0 + b) * SEQ + t]);
    }

    // gx(0): one float4 per (u, batch)
    float4 gxA, gxB;
    {
        const int tokA = __ldg(&x[(b0 + bA) * SEQ]);
        const int tokB = __ldg(&x[(b0 + bB) * SEQ]);
        gxA = *reinterpret_cast<const float4*>(g_emb_proj + (size_t)tokA * G4 + u * 4);
        gxB = *reinterpret_cast<const float4*>(g_emb_proj + (size_t)tokB * G4 + u * 4);
    }

    float cA = 0.f, cB = 0.f, hAv = 0.f, hBv = 0.f;

    __syncthreads();

    for (int t = 0; t < SEQ; t++) {
        const int buf = t & 1;
        const __half* hb = hS[buf];

        // ---- gx prefetch for t+1 (L2-resident; issued first for overlap) ----
        const int tn = (t + 1 < SEQ) ? (t + 1) : (SEQ - 1);
        const int tokA = tokS[bA][tn];
        const int tokB = tokS[bB][tn];
        float4 nA = *reinterpret_cast<const float4*>(g_emb_proj + (size_t)tokA * G4 + u * 4);
        float4 nB = *reinterpret_cast<const float4*>(g_emb_proj + (size_t)tokB * G4 + u * 4);

        // ---- 8 HMMA, split-K (K0,K1 -> chain a; K2,K3 -> chain b) ----
        float d0a=0.f,d1a=0.f,d2a=0.f,d3a=0.f, d0b=0.f,d1b=0.f,d2b=0.f,d3b=0.f;
        float e0a=0.f,e1a=0.f,e2a=0.f,e3a=0.f, e0b=0.f,e1b=0.f,e2b=0.f,e3b=0.f;
#pragma unroll
        for (int K = 0; K < 4; K++) {
            const int kk = 16 * K + 2 * t4;
            u32 bb0 = *reinterpret_cast<const u32*>(&hb[g * HSTRIDE + kk]);
            u32 bb1 = *reinterpret_cast<const u32*>(&hb[g * HSTRIDE + kk + 8]);
            if (K < 2) {
                hmma16816(d0a,d1a,d2a,d3a, A0[K][0],A0[K][1],A0[K][2],A0[K][3], bb0,bb1);
                hmma16816(e0a,e1a,e2a,e3a, A1[K][0],A1[K][1],A1[K][2],A1[K][3], bb0,bb1);
            } else {
                hmma16816(d0b,d1b,d2b,d3b, A0[K][0],A0[K][1],A0[K][2],A0[K][3], bb0,bb1);
                hmma16816(e0b,e1b,e2b,e3b, A1[K][0],A1[K][1],A1[K][2],A1[K][3], bb0,bb1);
            }
        }

        // ---- epilogue: all lanes, register-local ----
        // tile0: d0=i(u,bA) d1=i(u,bB) d2=f(u,bA) d3=f(u,bB); tile1: g/o same.
        float xi0 = d0a + d0b + gxA.x, xi1 = d1a + d1b + gxB.x;
        float xf0 = d2a + d2b + gxA.y, xf1 = d3a + d3b + gxB.y;
        float xg0 = e0a + e0b + gxA.z, xg1 = e1a + e1b + gxB.z;
        float xo0 = e2a + e2b + gxA.w, xo1 = e3a + e3b + gxB.w;

        u32 ti = h2tanh(pack_h2(0.5f * xi0, 0.5f * xi1));
        u32 tf = h2tanh(pack_h2(0.5f * xf0, 0.5f * xf1));
        u32 tg = h2tanh(pack_h2(xg0, xg1));
        u32 to = h2tanh(pack_h2(0.5f * xo0, 0.5f * xo1));
        half2 hti = *reinterpret_cast<half2*>(&ti);
        half2 htf = *reinterpret_cast<half2*>(&tf);
        half2 htg = *reinterpret_cast<half2*>(&tg);
        half2 hto = *reinterpret_cast<half2*>(&to);

        float i0 = fmaf(0.5f, __low2float(hti), 0.5f), i1 = fmaf(0.5f, __high2float(hti), 0.5f);
        float f0 = fmaf(0.5f, __low2float(htf), 0.5f), f1 = fmaf(0.5f, __high2float(htf), 0.5f);
        float g0 = __low2float(htg),                   g1 = __high2float(htg);
        float o0 = fmaf(0.5f, __low2float(hto), 0.5f), o1 = fmaf(0.5f, __high2float(hto), 0.5f);

        cA = fmaf(f0, cA, i0 * g0);
        cB = fmaf(f1, cB, i1 * g1);
        u32 tc = h2tanh(pack_h2(cA, cB));
        half2 htc = *reinterpret_cast<half2*>(&tc);
        hAv = o0 * __low2float(htc);
        hBv = o1 * __high2float(htc);

        // publish h(t+1)
        {
            __half* hn = hS[buf ^ 1];
            hn[bA * HSTRIDE + u] = __float2half(hAv);
            hn[bB * HSTRIDE + u] = __float2half(hBv);
        }
        gxA = nA; gxB = nB;

        __syncthreads();
    }

    g_hfin_h[(b0 + bA) * HID + u] = __float2half(hAv);
    g_hfin_h[(b0 + bB) * HID + u] = __float2half(hBv);
}

// ---------------------------------------------------------------------------
// K3: tensor-core FC, two-pass. store=0: exp row-sums -> g_partial.
// store=1: recompute, scale by g_rowinv, write normalized output once.
// (R9 version — measured good)
// ---------------------------------------------------------------------------
__global__ void __launch_bounds__(256) k3_fc(
    const float* __restrict__ W_fc, const float* __restrict__ b_fc,
    float* __restrict__ out, int store)
{
    __shared__ __align__(16) __half hs[64 * HSTRIDE];
    __shared__ float ws[8][64];
    __shared__ float riS[64];

    const int tid  = threadIdx.x;
    const int lane = tid & 31;
    const int w    = tid >> 5;
    const int g    = lane >> 2;
    const int t4   = lane & 3;

    const int cb   = blockIdx.x * 128;
    const int j1   = cb + 16 * w + g;
    const int j2   = j1 + 8;
    const bool v1  = (j1 < NUM_CITIES);
    const bool v2  = (j2 < NUM_CITIES);

    u32 A[4][4];
#pragma unroll
    for (int K = 0; K < 4; K++) {
        const int c = 16 * K + 2 * t4;
        A[K][0] = v1 ? w_half2(W_fc, j1, c)     : 0u;
        A[K][1] = v2 ? w_half2(W_fc, j2, c)     : 0u;
        A[K][2] = v1 ? w_half2(W_fc, j1, c + 8) : 0u;
        A[K][3] = v2 ? w_half2(W_fc, j2, c + 8) : 0u;
    }
    const float bias1 = v1 ? __ldg(&b_fc[j1]) : 0.0f;
    const float bias2 = v2 ? __ldg(&b_fc[j2]) : 0.0f;

    const u32* hsrc = reinterpret_cast<const u32*>(g_hfin_h);

    for (int chunk = 0; chunk < 16; chunk++) {
        const int cb64 = chunk * 64;
        __syncthreads();
        for (int i = tid; i < 64 * 32; i += 256) {
            const int r = i >> 5;
            const int cp = i & 31;
            *reinterpret_cast<u32*>(&hs[r * HSTRIDE + 2 * cp]) =
                __ldg(&hsrc[(cb64 + r) * 32 + cp]);
        }
        if (store && tid < 64) riS[tid] = g_rowinv[cb64 + tid];
        __syncthreads();

#pragma unroll
        for (int nt = 0; nt < 8; nt++) {
            const int nb = cb64 + nt * 8;
            float d0 = 0.f, d1 = 0.f, d2 = 0.f, d3 = 0.f;
#pragma unroll
            for (int K = 0; K < 4; K++) {
                const int kk = 16 * K + 2 * t4;
                const __half* hrow = &hs[(nt * 8 + g) * HSTRIDE];
                u32 bb0 = *reinterpret_cast<const u32*>(&hrow[kk]);
                u32 bb1 = *reinterpret_cast<const u32*>(&hrow[kk + 8]);
                hmma16816(d0, d1, d2, d3, A[K][0], A[K][1], A[K][2], A[K][3], bb0, bb1);
            }
            const float LOG2E = 1.4426950408889634f;
            float e0 = v1 ? fast_ex2((d0 + bias1) * LOG2E) : 0.0f;
            float e1 = v1 ? fast_ex2((d1 + bias1) * LOG2E) : 0.0f;
            float e2 = v2 ? fast_ex2((d2 + bias2) * LOG2E) : 0.0f;
            float e3 = v2 ? fast_ex2((d3 + bias2) * LOG2E) : 0.0f;

            if (store) {
                const float r0v = riS[nt * 8 + 2 * t4];
                const float r1v = riS[nt * 8 + 2 * t4 + 1];
                const size_t rA = (size_t)(nb + 2 * t4) * NUM_CITIES;
                const size_t rB = (size_t)(nb + 2 * t4 + 1) * NUM_CITIES;
                if (v1) { __stcs(&out[rA + j1], e0 * r0v); __stcs(&out[rB + j1], e1 * r1v); }
                if (v2) { __stcs(&out[rA + j2], e2 * r0v); __stcs(&out[rB + j2], e3 * r1v); }
            } else {
                float s0 = e0 + e2;
                float s1 = e1 + e3;
#pragma unroll
                for (int m = 4; m <= 16; m <<= 1) {
                    s0 += __shfl_xor_sync(0xffffffffu, s0, m);
                    s1 += __shfl_xor_sync(0xffffffffu, s1, m);
                }
                if (g == 0) {
                    ws[w][nt * 8 + 2 * t4]     = s0;
                    ws[w][nt * 8 + 2 * t4 + 1] = s1;
                }
            }
        }
        if (!store) {
            __syncthreads();
            if (tid < 64) {
                float s = 0.0f;
#pragma unroll
                for (int ww = 0; ww < 8; ww++) s += ws[ww][tid];
                g_partial[blockIdx.x * BATCH + cb64 + tid] = s;
            }
        }
    }
}

// ---------------------------------------------------------------------------
// K3c: exact row-sum inverses. One warp per batch row.
// ---------------------------------------------------------------------------
__global__ void __launch_bounds__(128) k3c_inv()
{
    const int warp = (blockIdx.x * 128 + threadIdx.x) >> 5;
    const int lane = threadIdx.x & 31;
    float s = 0.0f;
    for (int cta = lane; cta < K3_CTAS; cta += 32)
        s += g_partial[cta * BATCH + warp];
    s += __shfl_xor_sync(0xffffffffu, s, 16);
    s += __shfl_xor_sync(0xffffffffu, s, 8);
    s += __shfl_xor_sync(0xffffffffu, s, 4);
    s += __shfl_xor_sync(0xffffffffu, s, 2);
    s += __shfl_xor_sync(0xffffffffu, s, 1);
    if (lane == 0) g_rowinv[warp] = 1.0f / s;
}

// ---------------------------------------------------------------------------
extern "C" void kernel_launch(void* const* d_in, const int* in_sizes, int n_in,
                              void* d_out, int out_size)
{
    (void)in_sizes; (void)n_in; (void)out_size;
    const int*   x    = (const int*)  d_in[0];
    const float* emb  = (const float*)d_in[1];
    const float* W_ih = (const float*)d_in[2];
    const float* W_hh = (const float*)d_in[3];
    const float* b_ih = (const float*)d_in[4];
    const float* b_hh = (const float*)d_in[5];
    const float* W_fc = (const float*)d_in[6];
    const float* b_fc = (const float*)d_in[7];
    float* out = (float*)d_out;

    k1_embproj<<<NUM_CITIES / 80, 256>>>(emb, W_ih, b_ih, b_hh);
    k_nop<<<1, 32>>>();
    k_nop<<<1, 32>>>();
    k2_lstm<<<BATCH / 8, 256>>>(x, W_hh);          // launch idx 3 -> profiled
    k3_fc<<<K3_CTAS, 256>>>(W_fc, b_fc, out, 0);   // pass 1: sums
    k3c_inv<<<256, 128>>>();
    k3_fc<<<K3_CTAS, 256>>>(W_fc, b_fc, out, 1);   // pass 2: normalized store
}